// round 7
// baseline (speedup 1.0000x reference)
#include <cuda_runtime.h>
#include <cuda_fp16.h>
#include <math.h>

#define G       128
#define GG      16384
#define GGG     2097152
#define NL      200000
#define HALF_W  200.0f
#define DXC     3.125f
#define INV_DXC 0.32f
#define KW2F    28.274333882308138f        /* 9*pi */
#define INV2S2  0.070735530263064588f      /* 1/(4.5*pi) */
#define LOG2E   1.4426950408889634f

#define WORDS_PER_AXIS (16 * 128 * 32 * 128)   /* 8M words = 32MB */

// z-transposed uint8 volume: q8t[k*GG + i*G + j] = q8(image[i][j][k])
__device__ unsigned char g_q8t[GGG];
// Tiled per-axis layouts: [si*4+sj][k][i>>2][j][i&3], 16 shift copies each.
__device__ unsigned char g_TX[WORDS_PER_AXIS * 4];
__device__ unsigned char g_TY[WORDS_PER_AXIS * 4];
__device__ unsigned char g_TZ[WORDS_PER_AXIS * 4];

// ---- prep 1: coalesced transpose+quantize for the z layout -----------------
__global__ void transpose_q8(const float* __restrict__ img,
                             unsigned char* __restrict__ q8t) {
    __shared__ unsigned char tile[32][33];
    int r0 = blockIdx.x * 32;          // r = i*G + j
    int c0 = blockIdx.y * 32;          // c = k
    int tx = threadIdx.x, ty = threadIdx.y;   // 32 x 8
    #pragma unroll
    for (int dy = 0; dy < 32; dy += 8) {
        float f = img[(r0 + ty + dy) * G + c0 + tx];
        tile[ty + dy][tx] = (unsigned char)__float2uint_rn(f * 255.0f);
    }
    __syncthreads();
    #pragma unroll
    for (int dy = 0; dy < 32; dy += 8)
        q8t[(size_t)(c0 + ty + dy) * GG + r0 + tx] = tile[tx][ty + dy];
}

// ---- prep 2: smem-staged tiled-copy builder --------------------------------
#define ST_STRIDE 132
#define ST_ROWS   131

template <int AXIS>
__global__ void __launch_bounds__(256)
build_tiled(const float* __restrict__ img,
            const unsigned char* __restrict__ q8t,
            unsigned char* __restrict__ dst) {
    __shared__ unsigned char st[ST_ROWS * ST_STRIDE];   // st[jj*132 + ii]
    int k = blockIdx.x;
    int tid = threadIdx.x;

    for (int w = tid; w < ST_ROWS * ST_STRIDE / 4; w += 256)
        ((unsigned*)st)[w] = 0;
    __syncthreads();

    for (int it = tid; it < 128 * 32; it += 256) {
        int i = it >> 5, jw = it & 31;
        int j = jw * 4;
        if (AXIS == 2) {
            unsigned v = ((const unsigned*)(q8t + (size_t)k * GG + i * G))[jw];
            st[(j + 0) * ST_STRIDE + i] = v & 255;
            st[(j + 1) * ST_STRIDE + i] = (v >> 8) & 255;
            st[(j + 2) * ST_STRIDE + i] = (v >> 16) & 255;
            st[(j + 3) * ST_STRIDE + i] = v >> 24;
        } else {
            size_t base = (AXIS == 0) ? ((size_t)k * GG + i * G)
                                      : ((size_t)i * GG + k * G);
            float4 f = ((const float4*)(img + base))[jw];
            st[(j + 0) * ST_STRIDE + i] = (unsigned char)__float2uint_rn(f.x * 255.0f);
            st[(j + 1) * ST_STRIDE + i] = (unsigned char)__float2uint_rn(f.y * 255.0f);
            st[(j + 2) * ST_STRIDE + i] = (unsigned char)__float2uint_rn(f.z * 255.0f);
            st[(j + 3) * ST_STRIDE + i] = (unsigned char)__float2uint_rn(f.w * 255.0f);
        }
    }
    __syncthreads();

    unsigned* dw = (unsigned*)dst;
    for (int it = tid; it < 32 * 128; it += 256) {
        int j = it & 127, ti = it >> 7;
        #pragma unroll
        for (int sj = 0; sj < 4; sj++) {
            const unsigned* row = (const unsigned*)(st + (j + sj) * ST_STRIDE);
            unsigned w0 = row[ti];
            unsigned w1 = row[ti + 1];
            #pragma unroll
            for (int si = 0; si < 4; si++) {
                unsigned word = si ? __funnelshift_r(w0, w1, 8 * si) : w0;
                dw[((si * 4 + sj) << 19) | (k << 12) | (ti << 7) | j] = word;
            }
        }
    }
}

// ---- main projection: batch-4 software-pipelined loads ---------------------
template <int PX, int PY, int PZ>
__device__ __forceinline__ float project_one(const unsigned char* __restrict__ base,
                                             const float* __restrict__ l) {
    const float C1 = -INV2S2 * LOG2E;
    const float C3 = -2.0f * DXC * INV2S2 * LOG2E;
    const float C4 = -DXC * DXC * INV2S2 * LOG2E;
    const float Qc = exp2f(-2.0f * DXC * DXC * INV2S2 * LOG2E);

    float p0x = l[PX], p0y = l[PY], p0z = l[PZ];
    float dvx = l[PX + 3] - p0x;
    float dvy = l[PY + 3] - p0y;
    float dvz = l[PZ + 3] - p0z;

    float L = sqrtf(dvx * dvx + dvy * dvy + dvz * dvz);
    float inv_dzl = 1.0f / dvz;
    float path = DXC * L / fabsf(dvz);

    // ux(k), uy(k) affine in k
    float dt  = DXC * inv_dzl;
    float t0  = (0.5f * DXC - HALF_W - p0z) * inv_dzl;
    float dux = dt * dvx * INV_DXC;
    float duy = dt * dvy * INV_DXC;
    float ux0 = fmaf(t0, dvx, p0x + HALF_W) * INV_DXC;
    float uy0 = fmaf(t0, dvy, p0y + HALF_W) * INV_DXC;

    const __half2 H1024 = __float2half2_rn(1024.0f);
    float S = 0.0f;

    #pragma unroll 1
    for (int kb = 0; kb < G; kb += 4) {
        // ---- phase 1: compute 4 window starts, issue 4 independent loads
        uint4 q[4];
        float irf[4], stjf[4];
        #pragma unroll
        for (int u = 0; u < 4; u++) {
            int k = kb + u;
            float kf = (float)k;
            float ux = fmaf(kf, dux, ux0);
            float uy = fmaf(kf, duy, uy0);
            irf[u]  = fminf(fmaxf(floorf(ux - 1.5f), 0.0f), 124.0f);
            stjf[u] = fminf(fmaxf(floorf(uy - 1.5f), 0.0f), 124.0f);
            int ir  = (int)irf[u];
            int stj = (int)stjf[u];
            const uint4* p = (const uint4*)(base
                + (((size_t)(((ir & 3) << 2) | (stj & 3))) << 21)
                + (size_t)(((k << 5) + (ir >> 2)) << 9)
                + (size_t)((stj & ~3) << 2));
            q[u] = __ldg(p);
        }

        // ---- phase 2: compute against landed data
        #pragma unroll
        for (int u = 0; u < 4; u++) {
            float kf = (float)(kb + u);
            float ux = fmaf(kf, dux, ux0);
            float uy = fmaf(kf, duy, uy0);

            float dxr = fmaf(irf[u] - ux, DXC, 0.5f * DXC);
            float wx0 = exp2f(dxr * dxr * C1);
            float rx  = exp2f(fmaf(C3, dxr, C4));
            float wx[4], thr[4];
            #pragma unroll
            for (int r = 0; r < 4; r++) {
                float d = fmaf((float)r, DXC, dxr);
                thr[r] = KW2F - d * d;
                wx[r] = wx0;
                wx0 *= rx;
                rx  *= Qc;
            }

            float dy0 = fmaf(stjf[u] - uy, DXC, 0.5f * DXC);
            float wyc = exp2f(dy0 * dy0 * C1);
            float ry  = exp2f(fmaf(C3, dy0, C4));

            unsigned wq[4] = {q[u].x, q[u].y, q[u].z, q[u].w};
            float sl = 0.0f;
            #pragma unroll
            for (int c = 0; c < 4; c++) {
                float d   = fmaf((float)c, DXC, dy0);
                float dy2 = d * d;

                unsigned lo = __byte_perm(wq[c], 0x64646464u, 0x4140);
                unsigned hi = __byte_perm(wq[c], 0x64646464u, 0x4342);
                __half2 hlo = __hsub2(*(__half2*)&lo, H1024);
                __half2 hhi = __hsub2(*(__half2*)&hi, H1024);
                float2 f01 = __half22float2(hlo);
                float2 f23 = __half22float2(hhi);

                float sc;
                sc =      ((dy2 <= thr[0]) ? wx[0] : 0.0f) * f01.x;
                sc = fmaf(((dy2 <= thr[1]) ? wx[1] : 0.0f), f01.y, sc);
                sc = fmaf(((dy2 <= thr[2]) ? wx[2] : 0.0f), f23.x, sc);
                sc = fmaf(((dy2 <= thr[3]) ? wx[3] : 0.0f), f23.y, sc);
                sl = fmaf(wyc, sc, sl);

                wyc *= ry;
                ry  *= Qc;
            }
            S += sl;
        }
    }
    return S * path * (1.0f / 255.0f);
}

__global__ void __launch_bounds__(256, 4)
fused_proj(const float* __restrict__ xl,
           const float* __restrict__ yl,
           const float* __restrict__ zl,
           float* __restrict__ out) {
    int stride = gridDim.x * blockDim.x;
    for (int idx = blockIdx.x * blockDim.x + threadIdx.x; idx < 3 * NL; idx += stride) {
        float res;
        if (idx < NL) {
            res = project_one<1, 2, 0>(g_TX, xl + idx * 6);            // axis x
        } else if (idx < 2 * NL) {
            res = project_one<0, 2, 1>(g_TY, yl + (idx - NL) * 6);     // axis y
        } else {
            res = project_one<0, 1, 2>(g_TZ, zl + (idx - 2 * NL) * 6); // axis z
        }
        out[idx] = res;
    }
}

extern "C" void kernel_launch(void* const* d_in, const int* in_sizes, int n_in,
                              void* d_out, int out_size) {
    const float* image = (const float*)d_in[0];
    const float* xlors = (const float*)d_in[1];
    const float* ylors = (const float*)d_in[2];
    const float* zlors = (const float*)d_in[3];
    float* out = (float*)d_out;

    unsigned char *q8t, *tx, *ty, *tz;
    cudaGetSymbolAddress((void**)&q8t, g_q8t);
    cudaGetSymbolAddress((void**)&tx, g_TX);
    cudaGetSymbolAddress((void**)&ty, g_TY);
    cudaGetSymbolAddress((void**)&tz, g_TZ);

    transpose_q8<<<dim3(GG / 32, G / 32), dim3(32, 8)>>>(image, q8t);
    build_tiled<0><<<G, 256>>>(image, q8t, tx);
    build_tiled<1><<<G, 256>>>(image, q8t, ty);
    build_tiled<2><<<G, 256>>>(image, q8t, tz);

    fused_proj<<<740, 256>>>(xlors, ylors, zlors, out);
}